// round 13
// baseline (speedup 1.0000x reference)
#include <cuda_runtime.h>
#include <cuda_fp16.h>
#include <math.h>
#include <stdint.h>

// Shapes (fixed by the problem)
#define Bb   4
#define Tt   4096
#define Dm   1024
#define Kk   64
#define K2   128
#define Hh   4
#define Khd  16
#define NCH  64
#define BT   (Bb*Tt)       // 16384
#define MLP  4096
#define OUT_ELEMS (BT*Dm)  // 16777216

#define STAGES 3
#define TILE_BYTES 16384                         // 128 rows x 128 bytes (64 halves)
#define SMEM_BYTES (STAGES * 2 * TILE_BYTES)     // 98304

// ---------------- scratch (static device memory; no allocation) ----------------
__device__ __half g_xn     [BT*Dm];
__device__ float  g_beta_l [BT*K2];
__device__ __half g_eig_h  [BT*K2];
__device__ float  g_x1     [BT*Dm];
__device__ __half g_xn2    [BT*Dm];
__device__ __half g_hidden [BT*MLP];
// fp16 weight copies
__device__ __half g_w_in   [K2*Dm];
__device__ __half g_w_out  [Dm*K2];
__device__ __half g_w_gate [Dm*Dm];
__device__ __half g_w_m1   [MLP*Dm];
__device__ __half g_w_m2   [Dm*MLP];

// ---------------- helpers ----------------
__device__ __forceinline__ void cp_async16(void* smem_dst, const void* gptr) {
    unsigned saddr = (unsigned)__cvta_generic_to_shared(smem_dst);
    asm volatile("cp.async.cg.shared.global [%0], [%1], 16;\n" :: "r"(saddr), "l"(gptr));
}
__device__ __forceinline__ void cp_commit() { asm volatile("cp.async.commit_group;\n"); }
__device__ __forceinline__ void cp_wait1()  { asm volatile("cp.async.wait_group 1;\n"); }
__device__ __forceinline__ void cp_wait0()  { asm volatile("cp.async.wait_group 0;\n"); }

__device__ __forceinline__ void ldsm_x4(unsigned& r0, unsigned& r1, unsigned& r2, unsigned& r3,
                                        unsigned saddr) {
    asm volatile("ldmatrix.sync.aligned.m8n8.x4.shared.b16 {%0,%1,%2,%3}, [%4];"
                 : "=r"(r0), "=r"(r1), "=r"(r2), "=r"(r3) : "r"(saddr));
}

// ---------------- fused weight conversion fp32 -> fp16 (all 5 matrices) --------
#define SEG_M1   4194304
#define SEG_M2   8388608
#define SEG_GATE 9437184
#define SEG_IN   9568256
#define SEG_OUT  9699328
__global__ void convert_weights(const float* __restrict__ m1f, const float* __restrict__ m2f,
                                const float* __restrict__ gf,  const float* __restrict__ inf_,
                                const float* __restrict__ outf,
                                __half* __restrict__ m1h, __half* __restrict__ m2h,
                                __half* __restrict__ gh,  __half* __restrict__ inh,
                                __half* __restrict__ outh)
{
    int j = (blockIdx.x * blockDim.x + threadIdx.x) * 2;
    const float* src; __half* dst; int off;
    if      (j < SEG_M1)   { src = m1f;  dst = m1h;  off = j; }
    else if (j < SEG_M2)   { src = m2f;  dst = m2h;  off = j - SEG_M1; }
    else if (j < SEG_GATE) { src = gf;   dst = gh;   off = j - SEG_M2; }
    else if (j < SEG_IN)   { src = inf_; dst = inh;  off = j - SEG_GATE; }
    else if (j < SEG_OUT)  { src = outf; dst = outh; off = j - SEG_IN; }
    else return;
    float2 v = *(const float2*)(src + off);
    *(__half2*)(dst + off) = __floats2half2_rn(v.x, v.y);
}

// ---------------- LayerNorm (writes fp16 output) ----------------
__global__ void ln_kernel(const float* __restrict__ in, __half* __restrict__ out,
                          const float* __restrict__ g, const float* __restrict__ bta)
{
    int row = blockIdx.x;
    const float4* p = (const float4*)(in + (size_t)row * Dm);
    float4 v = p[threadIdx.x];
    float s  = v.x + v.y + v.z + v.w;
    float ss = v.x*v.x + v.y*v.y + v.z*v.z + v.w*v.w;
    #pragma unroll
    for (int o = 16; o > 0; o >>= 1) {
        s  += __shfl_down_sync(0xffffffffu, s,  o);
        ss += __shfl_down_sync(0xffffffffu, ss, o);
    }
    __shared__ float rs[8], rss[8];
    __shared__ float smean, srstd;
    int warp = threadIdx.x >> 5, lane = threadIdx.x & 31;
    if (lane == 0) { rs[warp] = s; rss[warp] = ss; }
    __syncthreads();
    if (threadIdx.x == 0) {
        float ts = 0.f, tss = 0.f;
        #pragma unroll
        for (int w = 0; w < 8; w++) { ts += rs[w]; tss += rss[w]; }
        float mean = ts * (1.f/Dm);
        float var  = tss * (1.f/Dm) - mean*mean;
        smean = mean;
        srstd = rsqrtf(var + 1e-5f);
    }
    __syncthreads();
    float mean = smean, rstd = srstd;
    float4 gg = ((const float4*)g)[threadIdx.x];
    float4 bb = ((const float4*)bta)[threadIdx.x];
    __half2 h0 = __floats2half2_rn((v.x - mean) * rstd * gg.x + bb.x,
                                   (v.y - mean) * rstd * gg.y + bb.y);
    __half2 h1 = __floats2half2_rn((v.z - mean) * rstd * gg.z + bb.z,
                                   (v.w - mean) * rstd * gg.w + bb.w);
    __half2* dst = (__half2*)(out + (size_t)row * Dm) + threadIdx.x * 2;
    dst[0] = h0;
    dst[1] = h1;
}

// ---------------- fp16 tensor GEMM, 3-stage cp.async pipeline + ldmatrix --------
// C[m][n] = sum_k A[m][k]*B[n][k]; A,B fp16 row-major, Kd % 64 == 0.
// Block 128x128, 8 warps (2x4), warp tile 64x32, mma m16n8k16 (fp32 accum).
// EPI 0: C = acc ; 1: silu(acc+bias) ; 3: acc + bias + aux1. HOUT: fp16 store.
template<int EPI, bool HOUT>
__global__ void __launch_bounds__(256)
gemm_fp16_kernel(const __half* __restrict__ A, const __half* __restrict__ Bw,
                 void* __restrict__ Cv, int M, int N, int Kd,
                 const float* __restrict__ bias,
                 const float* __restrict__ aux1)
{
    extern __shared__ char dsm[];
    const unsigned smem_u32 = (unsigned)__cvta_generic_to_shared(dsm);

    const int tid  = threadIdx.x;
    const int warp = tid >> 5, lane = tid & 31;
    const int wr = warp >> 2;
    const int wc = warp & 3;
    const int brow = blockIdx.y * 128, bcol = blockIdx.x * 128;

    const int lr  = tid >> 1;
    const int lcb = (tid & 1) * 4;
    const __half* Arow = A  + (size_t)(brow + lr) * Kd;
    const __half* Brow = Bw + (size_t)(bcol + lr) * Kd;

    const int KT = Kd >> 6;

    auto issue = [&](int buf, int k0) {
        char* Atile = dsm + buf * TILE_BYTES;
        char* Btile = dsm + (STAGES + buf) * TILE_BYTES;
        #pragma unroll
        for (int i = 0; i < 4; i++) {
            int cc = lcb + i;
            int dst = lr * 128 + (((cc ^ lr) & 7) << 4);
            cp_async16(Atile + dst, Arow + k0 + cc * 8);
            cp_async16(Btile + dst, Brow + k0 + cc * 8);
        }
    };

    float acc[4][4][4];
    #pragma unroll
    for (int m = 0; m < 4; m++)
        #pragma unroll
        for (int n = 0; n < 4; n++)
            #pragma unroll
            for (int i = 0; i < 4; i++) acc[m][n][i] = 0.f;

    issue(0, 0);  cp_commit();
    issue(1, 64); cp_commit();

    const int lm = lane & 7;
    int aoff[4], ars[4];
    {
        int rowsel = (lane >> 3) & 1;
        #pragma unroll
        for (int mt = 0; mt < 4; mt++) {
            int row = wr*64 + mt*16 + rowsel*8 + lm;
            aoff[mt] = row * 128;
            ars[mt]  = row & 7;
        }
    }
    const int ghA = lane >> 4;
    int boff[2], brs[2];
    {
        int rowsel = lane >> 4;
        #pragma unroll
        for (int p = 0; p < 2; p++) {
            int n = wc*32 + p*16 + rowsel*8 + lm;
            boff[p] = n * 128;
            brs[p]  = n & 7;
        }
    }
    const int ghB = (lane >> 3) & 1;

    const int ra = lane >> 2;
    const int c0 = lane & 3;

    for (int kt = 0; kt < KT; kt++) {
        cp_wait1();
        __syncthreads();
        if (kt + 2 < KT) issue((kt + 2) % STAGES, (kt + 2) * 64);
        cp_commit();

        const int buf = kt % STAGES;
        const unsigned Abase = smem_u32 + buf * TILE_BYTES;
        const unsigned Bbase = smem_u32 + (STAGES + buf) * TILE_BYTES;

        #pragma unroll
        for (int ks = 0; ks < 4; ks++) {
            unsigned af[4][4], bf[4][2];
            const int gA = 2*ks + ghA;
            #pragma unroll
            for (int mt = 0; mt < 4; mt++) {
                unsigned ad = Abase + aoff[mt] + (unsigned)(((gA ^ ars[mt]) & 7) << 4);
                ldsm_x4(af[mt][0], af[mt][1], af[mt][2], af[mt][3], ad);
            }
            const int gB = 2*ks + ghB;
            #pragma unroll
            for (int p = 0; p < 2; p++) {
                unsigned bd = Bbase + boff[p] + (unsigned)(((gB ^ brs[p]) & 7) << 4);
                ldsm_x4(bf[2*p][0], bf[2*p][1], bf[2*p+1][0], bf[2*p+1][1], bd);
            }
            #pragma unroll
            for (int mt = 0; mt < 4; mt++)
                #pragma unroll
                for (int nt = 0; nt < 4; nt++)
                    asm volatile(
                        "mma.sync.aligned.m16n8k16.row.col.f32.f16.f16.f32 "
                        "{%0,%1,%2,%3}, {%4,%5,%6,%7}, {%8,%9}, {%0,%1,%2,%3};"
                        : "+f"(acc[mt][nt][0]), "+f"(acc[mt][nt][1]),
                          "+f"(acc[mt][nt][2]), "+f"(acc[mt][nt][3])
                        : "r"(af[mt][0]), "r"(af[mt][1]), "r"(af[mt][2]), "r"(af[mt][3]),
                          "r"(bf[nt][0]), "r"(bf[nt][1]));
        }
    }

    #pragma unroll
    for (int mt = 0; mt < 4; mt++) {
        #pragma unroll
        for (int half = 0; half < 2; half++) {
            int row = brow + wr*64 + mt*16 + ra + half*8;
            #pragma unroll
            for (int nt = 0; nt < 4; nt++) {
                int col = bcol + wc*32 + nt*8 + c0*2;
                size_t idx = (size_t)row * N + col;
                float v0 = acc[mt][nt][half*2 + 0];
                float v1 = acc[mt][nt][half*2 + 1];
                float2 o;
                if (EPI == 0) {
                    o.x = v0; o.y = v1;
                } else if (EPI == 1) {
                    v0 += bias[col]; v1 += bias[col+1];
                    o.x = v0 / (1.f + expf(-v0));
                    o.y = v1 / (1.f + expf(-v1));
                } else { // EPI == 3
                    float2 a1v = *(const float2*)(aux1 + idx);
                    o.x = v0 + bias[col]   + a1v.x;
                    o.y = v1 + bias[col+1] + a1v.y;
                }
                if (HOUT) {
                    *(__half2*)((__half*)Cv + idx) = __floats2half2_rn(o.x, o.y);
                } else {
                    *(float2*)((float*)Cv + idx) = o;
                }
            }
        }
    }
}

// ---------------- fused gate+out_proj dual GEMM ----------------
// Phase 1: gate = xn @ gate_w.T (K=1024) -> g = sigmoid(gate+gate_b) parked fp16 in
//          the stage-2 SMEM tiles. Phase 2: h = eig_h @ out_proj_w.T (K=128).
// Epilogue: x1 = x + g * h.  Grid (8, 128), N = 1024.
__global__ void __launch_bounds__(256)
gemm_gate_kernel(const __half* __restrict__ Axn, const __half* __restrict__ Wg,
                 const __half* __restrict__ Aeig, const __half* __restrict__ Wo,
                 const float* __restrict__ xres, const float* __restrict__ gate_b,
                 float* __restrict__ x1)
{
    extern __shared__ char dsm[];
    const unsigned smem_u32 = (unsigned)__cvta_generic_to_shared(dsm);
    const int Nn = Dm;

    const int tid  = threadIdx.x;
    const int warp = tid >> 5, lane = tid & 31;
    const int wr = warp >> 2;
    const int wc = warp & 3;
    const int brow = blockIdx.y * 128, bcol = blockIdx.x * 128;

    const int lr  = tid >> 1;
    const int lcb = (tid & 1) * 4;
    const __half* Arow = Axn + (size_t)(brow + lr) * Dm;
    const __half* Brow = Wg  + (size_t)(bcol + lr) * Dm;

    const int KT = Dm >> 6;    // 16

    auto issue = [&](int buf, int k0) {
        char* Atile = dsm + buf * TILE_BYTES;
        char* Btile = dsm + (STAGES + buf) * TILE_BYTES;
        #pragma unroll
        for (int i = 0; i < 4; i++) {
            int cc = lcb + i;
            int dst = lr * 128 + (((cc ^ lr) & 7) << 4);
            cp_async16(Atile + dst, Arow + k0 + cc * 8);
            cp_async16(Btile + dst, Brow + k0 + cc * 8);
        }
    };

    float acc[4][4][4];
    #pragma unroll
    for (int m = 0; m < 4; m++)
        #pragma unroll
        for (int n = 0; n < 4; n++)
            #pragma unroll
            for (int i = 0; i < 4; i++) acc[m][n][i] = 0.f;

    issue(0, 0);  cp_commit();
    issue(1, 64); cp_commit();

    const int lm = lane & 7;
    int aoff[4], ars[4];
    {
        int rowsel = (lane >> 3) & 1;
        #pragma unroll
        for (int mt = 0; mt < 4; mt++) {
            int row = wr*64 + mt*16 + rowsel*8 + lm;
            aoff[mt] = row * 128;
            ars[mt]  = row & 7;
        }
    }
    const int ghA = lane >> 4;
    int boff[2], brs[2];
    {
        int rowsel = lane >> 4;
        #pragma unroll
        for (int p = 0; p < 2; p++) {
            int n = wc*32 + p*16 + rowsel*8 + lm;
            boff[p] = n * 128;
            brs[p]  = n & 7;
        }
    }
    const int ghB = (lane >> 3) & 1;

    const int ra = lane >> 2;
    const int c0 = lane & 3;

    // ---- phase 1: gate GEMM (K = 1024) ----
    for (int kt = 0; kt < KT; kt++) {
        cp_wait1();
        __syncthreads();
        if (kt + 2 < KT) issue((kt + 2) % STAGES, (kt + 2) * 64);
        cp_commit();

        const int buf = kt % STAGES;
        const unsigned Abase = smem_u32 + buf * TILE_BYTES;
        const unsigned Bbase = smem_u32 + (STAGES + buf) * TILE_BYTES;

        #pragma unroll
        for (int ks = 0; ks < 4; ks++) {
            unsigned af[4][4], bf[4][2];
            const int gA = 2*ks + ghA;
            #pragma unroll
            for (int mt = 0; mt < 4; mt++) {
                unsigned ad = Abase + aoff[mt] + (unsigned)(((gA ^ ars[mt]) & 7) << 4);
                ldsm_x4(af[mt][0], af[mt][1], af[mt][2], af[mt][3], ad);
            }
            const int gB = 2*ks + ghB;
            #pragma unroll
            for (int p = 0; p < 2; p++) {
                unsigned bd = Bbase + boff[p] + (unsigned)(((gB ^ brs[p]) & 7) << 4);
                ldsm_x4(bf[2*p][0], bf[2*p][1], bf[2*p+1][0], bf[2*p+1][1], bd);
            }
            #pragma unroll
            for (int mt = 0; mt < 4; mt++)
                #pragma unroll
                for (int nt = 0; nt < 4; nt++)
                    asm volatile(
                        "mma.sync.aligned.m16n8k16.row.col.f32.f16.f16.f32 "
                        "{%0,%1,%2,%3}, {%4,%5,%6,%7}, {%8,%9}, {%0,%1,%2,%3};"
                        : "+f"(acc[mt][nt][0]), "+f"(acc[mt][nt][1]),
                          "+f"(acc[mt][nt][2]), "+f"(acc[mt][nt][3])
                        : "r"(af[mt][0]), "r"(af[mt][1]), "r"(af[mt][2]), "r"(af[mt][3]),
                          "r"(bf[nt][0]), "r"(bf[nt][1]));
        }
    }

    // all warps done with phase-1 tiles before stage-2 region is repurposed for g
    __syncthreads();

    // g = sigmoid(acc + gate_b), parked fp16 in stage-2 A/B tiles (own-thread readback)
    #pragma unroll
    for (int mt = 0; mt < 4; mt++) {
        #pragma unroll
        for (int half = 0; half < 2; half++) {
            #pragma unroll
            for (int nt = 0; nt < 4; nt++) {
                int col = bcol + wc*32 + nt*8 + c0*2;
                float v0 = acc[mt][nt][half*2 + 0] + gate_b[col];
                float v1 = acc[mt][nt][half*2 + 1] + gate_b[col+1];
                __half2 gv = __floats2half2_rn(1.f / (1.f + expf(-v0)),
                                               1.f / (1.f + expf(-v1)));
                int j = mt*8 + half*4 + nt;          // 0..31
                unsigned w = (unsigned)(j * 256 + tid);
                char* gp = (w < 4096) ? (dsm + 2 * TILE_BYTES + w * 4)
                                      : (dsm + 5 * TILE_BYTES + (w - 4096) * 4);
                *(__half2*)gp = gv;
            }
        }
    }

    // zero acc for phase 2
    #pragma unroll
    for (int m = 0; m < 4; m++)
        #pragma unroll
        for (int n = 0; n < 4; n++)
            #pragma unroll
            for (int i = 0; i < 4; i++) acc[m][n][i] = 0.f;

    // ---- phase 2: out_proj GEMM (K = 128, buffers 0 and 1) ----
    {
        const __half* A2row = Aeig + (size_t)(brow + lr) * 128;
        const __half* B2row = Wo   + (size_t)(bcol + lr) * 128;
        #pragma unroll
        for (int bfi = 0; bfi < 2; bfi++) {
            int k0 = bfi * 64;
            #pragma unroll
            for (int i = 0; i < 4; i++) {
                int cc = lcb + i;
                int dst = lr * 128 + (((cc ^ lr) & 7) << 4);
                cp_async16(dsm + bfi * TILE_BYTES + dst, A2row + k0 + cc * 8);
                cp_async16(dsm + (STAGES + bfi) * TILE_BYTES + dst, B2row + k0 + cc * 8);
            }
        }
        cp_commit();
        cp_wait0();
    }
    __syncthreads();

    #pragma unroll
    for (int bfi = 0; bfi < 2; bfi++) {
        const unsigned Abase = smem_u32 + bfi * TILE_BYTES;
        const unsigned Bbase = smem_u32 + (STAGES + bfi) * TILE_BYTES;
        #pragma unroll
        for (int ks = 0; ks < 4; ks++) {
            unsigned af[4][4], bf[4][2];
            const int gA = 2*ks + ghA;
            #pragma unroll
            for (int mt = 0; mt < 4; mt++) {
                unsigned ad = Abase + aoff[mt] + (unsigned)(((gA ^ ars[mt]) & 7) << 4);
                ldsm_x4(af[mt][0], af[mt][1], af[mt][2], af[mt][3], ad);
            }
            const int gB = 2*ks + ghB;
            #pragma unroll
            for (int p = 0; p < 2; p++) {
                unsigned bd = Bbase + boff[p] + (unsigned)(((gB ^ brs[p]) & 7) << 4);
                ldsm_x4(bf[2*p][0], bf[2*p][1], bf[2*p+1][0], bf[2*p+1][1], bd);
            }
            #pragma unroll
            for (int mt = 0; mt < 4; mt++)
                #pragma unroll
                for (int nt = 0; nt < 4; nt++)
                    asm volatile(
                        "mma.sync.aligned.m16n8k16.row.col.f32.f16.f16.f32 "
                        "{%0,%1,%2,%3}, {%4,%5,%6,%7}, {%8,%9}, {%0,%1,%2,%3};"
                        : "+f"(acc[mt][nt][0]), "+f"(acc[mt][nt][1]),
                          "+f"(acc[mt][nt][2]), "+f"(acc[mt][nt][3])
                        : "r"(af[mt][0]), "r"(af[mt][1]), "r"(af[mt][2]), "r"(af[mt][3]),
                          "r"(bf[nt][0]), "r"(bf[nt][1]));
        }
    }

    // epilogue: x1 = x + g * h
    #pragma unroll
    for (int mt = 0; mt < 4; mt++) {
        #pragma unroll
        for (int half = 0; half < 2; half++) {
            int row = brow + wr*64 + mt*16 + ra + half*8;
            #pragma unroll
            for (int nt = 0; nt < 4; nt++) {
                int col = bcol + wc*32 + nt*8 + c0*2;
                size_t idx = (size_t)row * Nn + col;
                int j = mt*8 + half*4 + nt;
                unsigned w = (unsigned)(j * 256 + tid);
                const char* gp = (w < 4096) ? (dsm + 2 * TILE_BYTES + w * 4)
                                            : (dsm + 5 * TILE_BYTES + (w - 4096) * 4);
                float2 gv = __half22float2(*(const __half2*)gp);
                float2 xv = *(const float2*)(xres + idx);
                float2 o;
                o.x = xv.x + gv.x * acc[mt][nt][half*2 + 0];
                o.y = xv.y + gv.y * acc[mt][nt][half*2 + 1];
                *(float2*)(x1 + idx) = o;
            }
        }
    }
}

// ---------------- fused SSD: conv+SiLU + anti-causal scan + coupling + eig ------
__global__ void __launch_bounds__(256)
ssd_fused_kernel(const float* __restrict__ beta_l,
                 const float* __restrict__ conv_w,
                 const float* __restrict__ conv_b,
                 const float* __restrict__ log_decay,
                 const float* __restrict__ freq,
                 const float* __restrict__ coupling,
                 float* __restrict__ eig,
                 __half* __restrict__ eig_h)
{
    __shared__ float sb[64 * 128];
    __shared__ float scoup[Hh * Khd * Khd];
    int b  = blockIdx.x >> 6;
    int ch = blockIdx.x & 63;
    int tid = threadIdx.x;
    for (int i = tid; i < Hh * Khd * Khd; i += 256)
        scoup[i] = coupling[i];

    // conv + SiLU: thread = (column c, row-half hf); 32 rows each, streamed window
    {
        int c  = tid & 127;
        int hf = tid >> 7;
        int i0 = hf * 32;
        float w0 = conv_w[c*4+0], w1 = conv_w[c*4+1],
              w2 = conv_w[c*4+2], w3 = conv_w[c*4+3];
        float cb = conv_b[c];
        int t0 = ch * 64 + i0;                  // in-batch time of first output row
        size_t gbase = ((size_t)(b * Tt + t0)) * 128 + c;
        float p0 = (t0 - 3 >= 0) ? beta_l[gbase - 3*128] : 0.f;
        float p1 = (t0 - 2 >= 0) ? beta_l[gbase - 2*128] : 0.f;
        float p2 = (t0 - 1 >= 0) ? beta_l[gbase - 1*128] : 0.f;
        #pragma unroll 4
        for (int i = 0; i < 32; i++) {
            float cur = beta_l[gbase + (size_t)i * 128];
            float a = cb + p0*w0 + p1*w1 + p2*w2 + cur*w3;
            sb[(i0 + i) * 128 + c] = a / (1.f + expf(-a));
            p0 = p1; p1 = p2; p2 = cur;
        }
    }
    __syncthreads();

    if (tid < 64) {
        int k = tid;
        float mag = 1.f / (1.f + expf(-log_decay[k]));
        float f   = freq[k];
        float lr = mag * cosf(f), li = mag * sinf(f);
        float zr = 0.f, zi = 0.f;
        for (int i = 63; i >= 0; i--) {
            float br = sb[i * 128 + k];
            float bi = sb[i * 128 + 64 + k];
            float nr = lr * zr - li * zi + br;
            float ni = lr * zi + li * zr + bi;
            zr = nr; zi = ni;
            sb[i * 128 + k]      = zr;
            sb[i * 128 + 64 + k] = zi;
        }
        if (ch > 0) {
            // carry = silu(conv at t = ch*64-1) for channels k (real), 64+k (imag)
            size_t gb = ((size_t)(b * Tt + ch * 64 - 4)) * 128;
            float ar = conv_b[k], ai = conv_b[64 + k];
            #pragma unroll
            for (int j = 0; j < 4; j++) {
                ar += beta_l[gb + (size_t)j * 128 + k]      * conv_w[k * 4 + j];
                ai += beta_l[gb + (size_t)j * 128 + 64 + k] * conv_w[(64 + k) * 4 + j];
            }
            sb[k]      += ar / (1.f + expf(-ar));
            sb[64 + k] += ai / (1.f + expf(-ai));
        }
    }
    __syncthreads();

    for (int task = tid; task < 64 * 64; task += 256) {
        int i  = task >> 6;
        int ko = task & 63;
        int h = ko >> 4, j = ko & 15;
        const float* cw = scoup + h * (Khd * Khd) + j * Khd;
        const float* rowr = sb + i * 128 + h * Khd;
        const float* rowi = rowr + 64;
        float or_ = 0.f, oi_ = 0.f;
        #pragma unroll
        for (int kk = 0; kk < Khd; kk++) {
            float w = cw[kk];
            or_ += w * rowr[kk];
            oi_ += w * rowi[kk];
        }
        size_t e = (size_t)(b * Tt + ch * 64 + i) * 128;
        eig[e + ko]      = or_;
        eig[e + 64 + ko] = oi_;
        eig_h[e + ko]      = __float2half_rn(or_);
        eig_h[e + 64 + ko] = __float2half_rn(oi_);
    }
}

// ---------------- launcher ----------------
extern "C" void kernel_launch(void* const* d_in, const int* in_sizes, int n_in,
                              void* d_out, int out_size)
{
    const float* x          = (const float*)d_in[0];
    const float* in_proj_w  = (const float*)d_in[1];
    const float* conv_w     = (const float*)d_in[2];
    const float* conv_b     = (const float*)d_in[3];
    const float* log_decay  = (const float*)d_in[4];
    const float* frequency  = (const float*)d_in[5];
    const float* coupling   = (const float*)d_in[6];
    const float* out_proj_w = (const float*)d_in[7];
    const float* gate_w     = (const float*)d_in[8];
    const float* gate_b     = (const float*)d_in[9];
    const float* mlp_w1     = (const float*)d_in[10];
    const float* mlp_b1     = (const float*)d_in[11];
    const float* mlp_w2     = (const float*)d_in[12];
    const float* mlp_b2     = (const float*)d_in[13];
    const float* ln1_g      = (const float*)d_in[14];
    const float* ln1_b      = (const float*)d_in[15];
    const float* ln2_g      = (const float*)d_in[16];
    const float* ln2_b      = (const float*)d_in[17];

    float* out = (float*)d_out;
    float* eig = out + OUT_ELEMS;

    __half *xn, *xn2, *hidden, *eig_h;
    float  *beta_l, *x1;
    __half *w_in, *w_out, *w_gate, *w_m1, *w_m2;
    cudaGetSymbolAddress((void**)&xn,     g_xn);
    cudaGetSymbolAddress((void**)&beta_l, g_beta_l);
    cudaGetSymbolAddress((void**)&eig_h,  g_eig_h);
    cudaGetSymbolAddress((void**)&x1,     g_x1);
    cudaGetSymbolAddress((void**)&xn2,    g_xn2);
    cudaGetSymbolAddress((void**)&hidden, g_hidden);
    cudaGetSymbolAddress((void**)&w_in,   g_w_in);
    cudaGetSymbolAddress((void**)&w_out,  g_w_out);
    cudaGetSymbolAddress((void**)&w_gate, g_w_gate);
    cudaGetSymbolAddress((void**)&w_m1,   g_w_m1);
    cudaGetSymbolAddress((void**)&w_m2,   g_w_m2);

    cudaFuncSetAttribute(gemm_fp16_kernel<0,false>, cudaFuncAttributeMaxDynamicSharedMemorySize, SMEM_BYTES);
    cudaFuncSetAttribute(gemm_fp16_kernel<1,true>,  cudaFuncAttributeMaxDynamicSharedMemorySize, SMEM_BYTES);
    cudaFuncSetAttribute(gemm_fp16_kernel<3,false>, cudaFuncAttributeMaxDynamicSharedMemorySize, SMEM_BYTES);
    cudaFuncSetAttribute(gemm_gate_kernel,          cudaFuncAttributeMaxDynamicSharedMemorySize, SMEM_BYTES);

    // 0. convert all weights to fp16 (single kernel)
    convert_weights<<<(SEG_OUT/2 + 255)/256, 256>>>(mlp_w1, mlp_w2, gate_w, in_proj_w, out_proj_w,
                                                    w_m1, w_m2, w_gate, w_in, w_out);
    // 1. xn = fp16(LN1(x))
    ln_kernel<<<BT, 256>>>(x, xn, ln1_g, ln1_b);
    // 2. beta_lin = xn @ in_proj_w.T  (fp32 out)
    gemm_fp16_kernel<0,false><<<dim3(1, 128), 256, SMEM_BYTES>>>(xn, w_in, beta_l, BT, 128, 1024,
                                                                 nullptr, nullptr);
    // 3. SSD (conv+silu + reverse scan + carry + coupling) -> eig, eig_h
    ssd_fused_kernel<<<Bb * NCH, 256>>>(beta_l, conv_w, conv_b, log_decay, frequency,
                                        coupling, eig, eig_h);
    // 4. x1 = x + sigmoid(xn @ gate_w.T + gate_b) * (eig @ out_proj_w.T)  (fused dual GEMM)
    gemm_gate_kernel<<<dim3(8, 128), 256, SMEM_BYTES>>>(xn, w_gate, eig_h, w_out,
                                                        x, gate_b, x1);
    // 5. xn2 = fp16(LN2(x1))
    ln_kernel<<<BT, 256>>>(x1, xn2, ln2_g, ln2_b);
    // 6. hidden = fp16(silu(xn2 @ mlp_w1.T + b1))
    gemm_fp16_kernel<1,true><<<dim3(32, 128), 256, SMEM_BYTES>>>(xn2, w_m1, hidden, BT, 4096, 1024,
                                                                 mlp_b1, nullptr);
    // 7. out = x1 + hidden @ mlp_w2.T + b2
    gemm_fp16_kernel<3,false><<<dim3(8, 128), 256, SMEM_BYTES>>>(hidden, w_m2, out, BT, 1024, 4096,
                                                                 mlp_b2, x1);
}

// round 14
// speedup vs baseline: 1.3150x; 1.3150x over previous
#include <cuda_runtime.h>
#include <cuda_fp16.h>
#include <math.h>
#include <stdint.h>

// Shapes (fixed by the problem)
#define Bb   4
#define Tt   4096
#define Dm   1024
#define Kk   64
#define K2   128
#define Hh   4
#define Khd  16
#define NCH  64
#define BT   (Bb*Tt)       // 16384
#define MLP  4096
#define OUT_ELEMS (BT*Dm)  // 16777216

#define STAGES 3
#define BTILE_BYTES 16384                        // 128 rows x 128 bytes

// ---------------- scratch (static device memory; no allocation) ----------------
__device__ __half g_xn     [BT*Dm];
__device__ float  g_beta_l [BT*K2];
__device__ __half g_eig_h  [BT*K2];
__device__ float  g_x1     [BT*Dm];
__device__ __half g_xn2    [BT*Dm];
__device__ __half g_hidden [BT*MLP];
// fp16 weight copies
__device__ __half g_w_in   [K2*Dm];
__device__ __half g_w_out  [Dm*K2];
__device__ __half g_w_gate [Dm*Dm];
__device__ __half g_w_m1   [MLP*Dm];
__device__ __half g_w_m2   [Dm*MLP];

// ---------------- helpers ----------------
__device__ __forceinline__ void cp_async16(void* smem_dst, const void* gptr) {
    unsigned saddr = (unsigned)__cvta_generic_to_shared(smem_dst);
    asm volatile("cp.async.cg.shared.global [%0], [%1], 16;\n" :: "r"(saddr), "l"(gptr));
}
__device__ __forceinline__ void cp_commit() { asm volatile("cp.async.commit_group;\n"); }
__device__ __forceinline__ void cp_wait1()  { asm volatile("cp.async.wait_group 1;\n"); }

__device__ __forceinline__ void ldsm_x4(unsigned& r0, unsigned& r1, unsigned& r2, unsigned& r3,
                                        unsigned saddr) {
    asm volatile("ldmatrix.sync.aligned.m8n8.x4.shared.b16 {%0,%1,%2,%3}, [%4];"
                 : "=r"(r0), "=r"(r1), "=r"(r2), "=r"(r3) : "r"(saddr));
}

// ---------------- fused weight conversion fp32 -> fp16 (all 5 matrices) --------
#define SEG_M1   4194304
#define SEG_M2   8388608
#define SEG_GATE 9437184
#define SEG_IN   9568256
#define SEG_OUT  9699328
__global__ void convert_weights(const float* __restrict__ m1f, const float* __restrict__ m2f,
                                const float* __restrict__ gf,  const float* __restrict__ inf_,
                                const float* __restrict__ outf,
                                __half* __restrict__ m1h, __half* __restrict__ m2h,
                                __half* __restrict__ gh,  __half* __restrict__ inh,
                                __half* __restrict__ outh)
{
    int j = (blockIdx.x * blockDim.x + threadIdx.x) * 2;
    const float* src; __half* dst; int off;
    if      (j < SEG_M1)   { src = m1f;  dst = m1h;  off = j; }
    else if (j < SEG_M2)   { src = m2f;  dst = m2h;  off = j - SEG_M1; }
    else if (j < SEG_GATE) { src = gf;   dst = gh;   off = j - SEG_M2; }
    else if (j < SEG_IN)   { src = inf_; dst = inh;  off = j - SEG_GATE; }
    else if (j < SEG_OUT)  { src = outf; dst = outh; off = j - SEG_IN; }
    else return;
    float2 v = *(const float2*)(src + off);
    *(__half2*)(dst + off) = __floats2half2_rn(v.x, v.y);
}

// ---------------- LayerNorm (writes fp16 output) ----------------
__global__ void ln_kernel(const float* __restrict__ in, __half* __restrict__ out,
                          const float* __restrict__ g, const float* __restrict__ bta)
{
    int row = blockIdx.x;
    const float4* p = (const float4*)(in + (size_t)row * Dm);
    float4 v = p[threadIdx.x];
    float s  = v.x + v.y + v.z + v.w;
    float ss = v.x*v.x + v.y*v.y + v.z*v.z + v.w*v.w;
    #pragma unroll
    for (int o = 16; o > 0; o >>= 1) {
        s  += __shfl_down_sync(0xffffffffu, s,  o);
        ss += __shfl_down_sync(0xffffffffu, ss, o);
    }
    __shared__ float rs[8], rss[8];
    __shared__ float smean, srstd;
    int warp = threadIdx.x >> 5, lane = threadIdx.x & 31;
    if (lane == 0) { rs[warp] = s; rss[warp] = ss; }
    __syncthreads();
    if (threadIdx.x == 0) {
        float ts = 0.f, tss = 0.f;
        #pragma unroll
        for (int w = 0; w < 8; w++) { ts += rs[w]; tss += rss[w]; }
        float mean = ts * (1.f/Dm);
        float var  = tss * (1.f/Dm) - mean*mean;
        smean = mean;
        srstd = rsqrtf(var + 1e-5f);
    }
    __syncthreads();
    float mean = smean, rstd = srstd;
    float4 gg = ((const float4*)g)[threadIdx.x];
    float4 bb = ((const float4*)bta)[threadIdx.x];
    __half2 h0 = __floats2half2_rn((v.x - mean) * rstd * gg.x + bb.x,
                                   (v.y - mean) * rstd * gg.y + bb.y);
    __half2 h1 = __floats2half2_rn((v.z - mean) * rstd * gg.z + bb.z,
                                   (v.w - mean) * rstd * gg.w + bb.w);
    __half2* dst = (__half2*)(out + (size_t)row * Dm) + threadIdx.x * 2;
    dst[0] = h0;
    dst[1] = h1;
}

// ---------------- fp16 tensor GEMM, 3-stage cp.async pipeline + ldmatrix --------
// C[m][n] = sum_k A[m][k]*B[n][k]; A,B fp16 row-major, Kd % 64 == 0.
// Block MROWS x 128, 8 warps (2 x 4), warp tile (MROWS/2) x 32, mma m16n8k16.
// EPI 0: C = acc ; 1: silu(acc+bias) ; 3: acc + bias + aux1. HOUT: fp16 store.
template<int EPI, bool HOUT, int MROWS>
__global__ void __launch_bounds__(256)
gemm_fp16_kernel(const __half* __restrict__ A, const __half* __restrict__ Bw,
                 void* __restrict__ Cv, int M, int N, int Kd,
                 const float* __restrict__ bias,
                 const float* __restrict__ aux1)
{
    constexpr int MTC   = MROWS / 32;       // mt tiles per warp (4 or 2)
    constexpr int ATILE = MROWS * 128;      // bytes per A stage
    extern __shared__ char dsm[];
    const unsigned smem_u32 = (unsigned)__cvta_generic_to_shared(dsm);

    const int tid  = threadIdx.x;
    const int warp = tid >> 5, lane = tid & 31;
    const int wr = warp >> 2;
    const int wc = warp & 3;
    const int brow = blockIdx.y * MROWS, bcol = blockIdx.x * 128;

    const int KT = Kd >> 6;

    auto issue = [&](int buf, int k0) {
        char* Atile = dsm + buf * ATILE;
        char* Btile = dsm + STAGES * ATILE + buf * BTILE_BYTES;
        #pragma unroll
        for (int i = 0; i < MROWS / 32; i++) {
            int L = tid + i * 256;
            int row = L >> 3, c16 = L & 7;
            cp_async16(Atile + row * 128 + (((c16 ^ row) & 7) << 4),
                       A + (size_t)(brow + row) * Kd + k0 + c16 * 8);
        }
        #pragma unroll
        for (int i = 0; i < 4; i++) {
            int L = tid + i * 256;
            int row = L >> 3, c16 = L & 7;
            cp_async16(Btile + row * 128 + (((c16 ^ row) & 7) << 4),
                       Bw + (size_t)(bcol + row) * Kd + k0 + c16 * 8);
        }
    };

    float acc[MTC][4][4];
    #pragma unroll
    for (int m = 0; m < MTC; m++)
        #pragma unroll
        for (int n = 0; n < 4; n++)
            #pragma unroll
            for (int i = 0; i < 4; i++) acc[m][n][i] = 0.f;

    issue(0, 0);  cp_commit();
    issue(1, 64); cp_commit();

    const int lm = lane & 7;
    int aoff[MTC], ars[MTC];
    {
        int rowsel = (lane >> 3) & 1;
        #pragma unroll
        for (int mt = 0; mt < MTC; mt++) {
            int row = wr * (MTC * 16) + mt * 16 + rowsel * 8 + lm;
            aoff[mt] = row * 128;
            ars[mt]  = row & 7;
        }
    }
    const int ghA = lane >> 4;
    int boff[2], brs[2];
    {
        int rowsel = lane >> 4;
        #pragma unroll
        for (int p = 0; p < 2; p++) {
            int n = wc*32 + p*16 + rowsel*8 + lm;
            boff[p] = n * 128;
            brs[p]  = n & 7;
        }
    }
    const int ghB = (lane >> 3) & 1;

    const int ra = lane >> 2;
    const int c0 = lane & 3;

    for (int kt = 0; kt < KT; kt++) {
        cp_wait1();
        __syncthreads();
        if (kt + 2 < KT) issue((kt + 2) % STAGES, (kt + 2) * 64);
        cp_commit();

        const int buf = kt % STAGES;
        const unsigned Abase = smem_u32 + buf * ATILE;
        const unsigned Bbase = smem_u32 + STAGES * ATILE + buf * BTILE_BYTES;

        #pragma unroll
        for (int ks = 0; ks < 4; ks++) {
            unsigned af[MTC][4], bf[4][2];
            const int gA = 2*ks + ghA;
            #pragma unroll
            for (int mt = 0; mt < MTC; mt++) {
                unsigned ad = Abase + aoff[mt] + (unsigned)(((gA ^ ars[mt]) & 7) << 4);
                ldsm_x4(af[mt][0], af[mt][1], af[mt][2], af[mt][3], ad);
            }
            const int gB = 2*ks + ghB;
            #pragma unroll
            for (int p = 0; p < 2; p++) {
                unsigned bd = Bbase + boff[p] + (unsigned)(((gB ^ brs[p]) & 7) << 4);
                ldsm_x4(bf[2*p][0], bf[2*p][1], bf[2*p+1][0], bf[2*p+1][1], bd);
            }
            #pragma unroll
            for (int mt = 0; mt < MTC; mt++)
                #pragma unroll
                for (int nt = 0; nt < 4; nt++)
                    asm volatile(
                        "mma.sync.aligned.m16n8k16.row.col.f32.f16.f16.f32 "
                        "{%0,%1,%2,%3}, {%4,%5,%6,%7}, {%8,%9}, {%0,%1,%2,%3};"
                        : "+f"(acc[mt][nt][0]), "+f"(acc[mt][nt][1]),
                          "+f"(acc[mt][nt][2]), "+f"(acc[mt][nt][3])
                        : "r"(af[mt][0]), "r"(af[mt][1]), "r"(af[mt][2]), "r"(af[mt][3]),
                          "r"(bf[nt][0]), "r"(bf[nt][1]));
        }
    }

    #pragma unroll
    for (int mt = 0; mt < MTC; mt++) {
        #pragma unroll
        for (int half = 0; half < 2; half++) {
            int row = brow + wr * (MTC * 16) + mt*16 + ra + half*8;
            #pragma unroll
            for (int nt = 0; nt < 4; nt++) {
                int col = bcol + wc*32 + nt*8 + c0*2;
                size_t idx = (size_t)row * N + col;
                float v0 = acc[mt][nt][half*2 + 0];
                float v1 = acc[mt][nt][half*2 + 1];
                float2 o;
                if (EPI == 0) {
                    o.x = v0; o.y = v1;
                } else if (EPI == 1) {
                    v0 += bias[col]; v1 += bias[col+1];
                    o.x = v0 / (1.f + expf(-v0));
                    o.y = v1 / (1.f + expf(-v1));
                } else { // EPI == 3
                    float2 a1v = *(const float2*)(aux1 + idx);
                    o.x = v0 + bias[col]   + a1v.x;
                    o.y = v1 + bias[col+1] + a1v.y;
                }
                if (HOUT) {
                    *(__half2*)((__half*)Cv + idx) = __floats2half2_rn(o.x, o.y);
                } else {
                    *(float2*)((float*)Cv + idx) = o;
                }
            }
        }
    }
}

#define SMEM_128 (STAGES * 2 * BTILE_BYTES)                 // 98304
#define SMEM_64  (STAGES * (64*128) + STAGES * BTILE_BYTES) // 73728

// ---------------- fused gate+out_proj dual GEMM ----------------
// Phase-2 operands (eig_h, Wo) prefetched at kernel entry into dedicated SMEM.
// Phase 1: gate = xn @ gate_w.T (K=1024) -> g = sigmoid(gate+gate_b) parked fp16.
// Phase 2: h = eig_h @ out_proj_w.T (K=128) from prefetched tiles (no load stall).
// Epilogue: x1 = x + g * h.  Grid (8, 128), N = 1024.
#define GK_A2  (STAGES * 2 * BTILE_BYTES)        // 98304: 2 x 16KB A2 buffers
#define GK_B2  (GK_A2 + 32768)                   // 2 x 16KB B2 buffers
#define GK_G   (GK_B2 + 32768)                   // 32KB g park
#define GK_SMEM (GK_G + 32768)                   // 196608
__global__ void __launch_bounds__(256)
gemm_gate_kernel(const __half* __restrict__ Axn, const __half* __restrict__ Wg,
                 const __half* __restrict__ Aeig, const __half* __restrict__ Wo,
                 const float* __restrict__ xres, const float* __restrict__ gate_b,
                 float* __restrict__ x1)
{
    extern __shared__ char dsm[];
    const unsigned smem_u32 = (unsigned)__cvta_generic_to_shared(dsm);
    const int Nn = Dm;

    const int tid  = threadIdx.x;
    const int warp = tid >> 5, lane = tid & 31;
    const int wr = warp >> 2;
    const int wc = warp & 3;
    const int brow = blockIdx.y * 128, bcol = blockIdx.x * 128;

    const int KT = Dm >> 6;    // 16

    // prefetch phase-2 operands as the FIRST cp.async group (drains at kt=0 wait)
    #pragma unroll
    for (int bfi = 0; bfi < 2; bfi++) {
        #pragma unroll
        for (int i = 0; i < 4; i++) {
            int L = tid + i * 256;
            int row = L >> 3, c16 = L & 7;
            int dst = row * 128 + (((c16 ^ row) & 7) << 4);
            cp_async16(dsm + GK_A2 + bfi * 16384 + dst,
                       Aeig + (size_t)(brow + row) * 128 + bfi * 64 + c16 * 8);
            cp_async16(dsm + GK_B2 + bfi * 16384 + dst,
                       Wo   + (size_t)(bcol + row) * 128 + bfi * 64 + c16 * 8);
        }
    }
    cp_commit();

    auto issue = [&](int buf, int k0) {
        char* Atile = dsm + buf * BTILE_BYTES;
        char* Btile = dsm + STAGES * BTILE_BYTES + buf * BTILE_BYTES;
        #pragma unroll
        for (int i = 0; i < 4; i++) {
            int L = tid + i * 256;
            int row = L >> 3, c16 = L & 7;
            int dst = row * 128 + (((c16 ^ row) & 7) << 4);
            cp_async16(Atile + dst, Axn + (size_t)(brow + row) * Dm + k0 + c16 * 8);
            cp_async16(Btile + dst, Wg  + (size_t)(bcol + row) * Dm + k0 + c16 * 8);
        }
    };

    float acc[4][4][4];
    #pragma unroll
    for (int m = 0; m < 4; m++)
        #pragma unroll
        for (int n = 0; n < 4; n++)
            #pragma unroll
            for (int i = 0; i < 4; i++) acc[m][n][i] = 0.f;

    issue(0, 0);  cp_commit();
    issue(1, 64); cp_commit();

    const int lm = lane & 7;
    int aoff[4], ars[4];
    {
        int rowsel = (lane >> 3) & 1;
        #pragma unroll
        for (int mt = 0; mt < 4; mt++) {
            int row = wr*64 + mt*16 + rowsel*8 + lm;
            aoff[mt] = row * 128;
            ars[mt]  = row & 7;
        }
    }
    const int ghA = lane >> 4;
    int boff[2], brs[2];
    {
        int rowsel = lane >> 4;
        #pragma unroll
        for (int p = 0; p < 2; p++) {
            int n = wc*32 + p*16 + rowsel*8 + lm;
            boff[p] = n * 128;
            brs[p]  = n & 7;
        }
    }
    const int ghB = (lane >> 3) & 1;

    const int ra = lane >> 2;
    const int c0 = lane & 3;

    // ---- phase 1: gate GEMM (K = 1024) ----
    for (int kt = 0; kt < KT; kt++) {
        cp_wait1();
        __syncthreads();
        if (kt + 2 < KT) issue((kt + 2) % STAGES, (kt + 2) * 64);
        cp_commit();

        const int buf = kt % STAGES;
        const unsigned Abase = smem_u32 + buf * BTILE_BYTES;
        const unsigned Bbase = smem_u32 + STAGES * BTILE_BYTES + buf * BTILE_BYTES;

        #pragma unroll
        for (int ks = 0; ks < 4; ks++) {
            unsigned af[4][4], bf[4][2];
            const int gA = 2*ks + ghA;
            #pragma unroll
            for (int mt = 0; mt < 4; mt++) {
                unsigned ad = Abase + aoff[mt] + (unsigned)(((gA ^ ars[mt]) & 7) << 4);
                ldsm_x4(af[mt][0], af[mt][1], af[mt][2], af[mt][3], ad);
            }
            const int gB = 2*ks + ghB;
            #pragma unroll
            for (int p = 0; p < 2; p++) {
                unsigned bd = Bbase + boff[p] + (unsigned)(((gB ^ brs[p]) & 7) << 4);
                ldsm_x4(bf[2*p][0], bf[2*p][1], bf[2*p+1][0], bf[2*p+1][1], bd);
            }
            #pragma unroll
            for (int mt = 0; mt < 4; mt++)
                #pragma unroll
                for (int nt = 0; nt < 4; nt++)
                    asm volatile(
                        "mma.sync.aligned.m16n8k16.row.col.f32.f16.f16.f32 "
                        "{%0,%1,%2,%3}, {%4,%5,%6,%7}, {%8,%9}, {%0,%1,%2,%3};"
                        : "+f"(acc[mt][nt][0]), "+f"(acc[mt][nt][1]),
                          "+f"(acc[mt][nt][2]), "+f"(acc[mt][nt][3])
                        : "r"(af[mt][0]), "r"(af[mt][1]), "r"(af[mt][2]), "r"(af[mt][3]),
                          "r"(bf[nt][0]), "r"(bf[nt][1]));
        }
    }

    // g = sigmoid(acc + gate_b), parked fp16 in dedicated region (own-thread readback)
    #pragma unroll
    for (int mt = 0; mt < 4; mt++) {
        #pragma unroll
        for (int half = 0; half < 2; half++) {
            #pragma unroll
            for (int nt = 0; nt < 4; nt++) {
                int col = bcol + wc*32 + nt*8 + c0*2;
                float v0 = acc[mt][nt][half*2 + 0] + gate_b[col];
                float v1 = acc[mt][nt][half*2 + 1] + gate_b[col+1];
                __half2 gv = __floats2half2_rn(1.f / (1.f + expf(-v0)),
                                               1.f / (1.f + expf(-v1)));
                int j = mt*8 + half*4 + nt;          // 0..31
                *(__half2*)(dsm + GK_G + (j * 256 + tid) * 4) = gv;
            }
        }
    }

    // zero acc for phase 2
    #pragma unroll
    for (int m = 0; m < 4; m++)
        #pragma unroll
        for (int n = 0; n < 4; n++)
            #pragma unroll
            for (int i = 0; i < 4; i++) acc[m][n][i] = 0.f;

    // ---- phase 2: out_proj GEMM (K = 128) from prefetched tiles ----
    #pragma unroll
    for (int bfi = 0; bfi < 2; bfi++) {
        const unsigned Abase = smem_u32 + GK_A2 + bfi * 16384;
        const unsigned Bbase = smem_u32 + GK_B2 + bfi * 16384;
        #pragma unroll
        for (int ks = 0; ks < 4; ks++) {
            unsigned af[4][4], bf[4][2];
            const int gA = 2*ks + ghA;
            #pragma unroll
            for (int mt = 0; mt < 4; mt++) {
                unsigned ad = Abase + aoff[mt] + (unsigned)(((gA ^ ars[mt]) & 7) << 4);
                ldsm_x4(af[mt][0], af[mt][1], af[mt][2], af[mt][3], ad);
            }
            const int gB = 2*ks + ghB;
            #pragma unroll
            for (int p = 0; p < 2; p++) {
                unsigned bd = Bbase + boff[p] + (unsigned)(((gB ^ brs[p]) & 7) << 4);
                ldsm_x4(bf[2*p][0], bf[2*p][1], bf[2*p+1][0], bf[2*p+1][1], bd);
            }
            #pragma unroll
            for (int mt = 0; mt < 4; mt++)
                #pragma unroll
                for (int nt = 0; nt < 4; nt++)
                    asm volatile(
                        "mma.sync.aligned.m16n8k16.row.col.f32.f16.f16.f32 "
                        "{%0,%1,%2,%3}, {%4,%5,%6,%7}, {%8,%9}, {%0,%1,%2,%3};"
                        : "+f"(acc[mt][nt][0]), "+f"(acc[mt][nt][1]),
                          "+f"(acc[mt][nt][2]), "+f"(acc[mt][nt][3])
                        : "r"(af[mt][0]), "r"(af[mt][1]), "r"(af[mt][2]), "r"(af[mt][3]),
                          "r"(bf[nt][0]), "r"(bf[nt][1]));
        }
    }

    // epilogue: x1 = x + g * h
    #pragma unroll
    for (int mt = 0; mt < 4; mt++) {
        #pragma unroll
        for (int half = 0; half < 2; half++) {
            int row = brow + wr*64 + mt*16 + ra + half*8;
            #pragma unroll
            for (int nt = 0; nt < 4; nt++) {
                int col = bcol + wc*32 + nt*8 + c0*2;
                size_t idx = (size_t)row * Nn + col;
                int j = mt*8 + half*4 + nt;
                float2 gv = __half22float2(*(const __half2*)(dsm + GK_G + (j * 256 + tid) * 4));
                float2 xv = *(const float2*)(xres + idx);
                float2 o;
                o.x = xv.x + gv.x * acc[mt][nt][half*2 + 0];
                o.y = xv.y + gv.y * acc[mt][nt][half*2 + 1];
                *(float2*)(x1 + idx) = o;
            }
        }
    }
}

// ---------------- fused SSD: conv+SiLU + anti-causal scan + coupling + eig ------
__global__ void __launch_bounds__(256)
ssd_fused_kernel(const float* __restrict__ beta_l,
                 const float* __restrict__ conv_w,
                 const float* __restrict__ conv_b,
                 const float* __restrict__ log_decay,
                 const float* __restrict__ freq,
                 const float* __restrict__ coupling,
                 float* __restrict__ eig,
                 __half* __restrict__ eig_h)
{
    __shared__ float sb[64 * 128];
    __shared__ float scoup[Hh * Khd * Khd];
    int b  = blockIdx.x >> 6;
    int ch = blockIdx.x & 63;
    int tid = threadIdx.x;
    for (int i = tid; i < Hh * Khd * Khd; i += 256)
        scoup[i] = coupling[i];

    // conv + SiLU: thread = (column c, row-half hf); 32 rows each, streamed window
    {
        int c  = tid & 127;
        int hf = tid >> 7;
        int i0 = hf * 32;
        float w0 = conv_w[c*4+0], w1 = conv_w[c*4+1],
              w2 = conv_w[c*4+2], w3 = conv_w[c*4+3];
        float cb = conv_b[c];
        int t0 = ch * 64 + i0;
        size_t gbase = ((size_t)(b * Tt + t0)) * 128 + c;
        float p0 = (t0 - 3 >= 0) ? beta_l[gbase - 3*128] : 0.f;
        float p1 = (t0 - 2 >= 0) ? beta_l[gbase - 2*128] : 0.f;
        float p2 = (t0 - 1 >= 0) ? beta_l[gbase - 1*128] : 0.f;
        #pragma unroll 4
        for (int i = 0; i < 32; i++) {
            float cur = beta_l[gbase + (size_t)i * 128];
            float a = cb + p0*w0 + p1*w1 + p2*w2 + cur*w3;
            sb[(i0 + i) * 128 + c] = a / (1.f + expf(-a));
            p0 = p1; p1 = p2; p2 = cur;
        }
    }
    __syncthreads();

    if (tid < 64) {
        int k = tid;
        float mag = 1.f / (1.f + expf(-log_decay[k]));
        float f   = freq[k];
        float lr = mag * cosf(f), li = mag * sinf(f);
        float zr = 0.f, zi = 0.f;
        for (int i = 63; i >= 0; i--) {
            float br = sb[i * 128 + k];
            float bi = sb[i * 128 + 64 + k];
            float nr = lr * zr - li * zi + br;
            float ni = lr * zi + li * zr + bi;
            zr = nr; zi = ni;
            sb[i * 128 + k]      = zr;
            sb[i * 128 + 64 + k] = zi;
        }
        if (ch > 0) {
            size_t gb = ((size_t)(b * Tt + ch * 64 - 4)) * 128;
            float ar = conv_b[k], ai = conv_b[64 + k];
            #pragma unroll
            for (int j = 0; j < 4; j++) {
                ar += beta_l[gb + (size_t)j * 128 + k]      * conv_w[k * 4 + j];
                ai += beta_l[gb + (size_t)j * 128 + 64 + k] * conv_w[(64 + k) * 4 + j];
            }
            sb[k]      += ar / (1.f + expf(-ar));
            sb[64 + k] += ai / (1.f + expf(-ai));
        }
    }
    __syncthreads();

    for (int task = tid; task < 64 * 64; task += 256) {
        int i  = task >> 6;
        int ko = task & 63;
        int h = ko >> 4, j = ko & 15;
        const float* cw = scoup + h * (Khd * Khd) + j * Khd;
        const float* rowr = sb + i * 128 + h * Khd;
        const float* rowi = rowr + 64;
        float or_ = 0.f, oi_ = 0.f;
        #pragma unroll
        for (int kk = 0; kk < Khd; kk++) {
            float w = cw[kk];
            or_ += w * rowr[kk];
            oi_ += w * rowi[kk];
        }
        size_t e = (size_t)(b * Tt + ch * 64 + i) * 128;
        eig[e + ko]      = or_;
        eig[e + 64 + ko] = oi_;
        eig_h[e + ko]      = __float2half_rn(or_);
        eig_h[e + 64 + ko] = __float2half_rn(oi_);
    }
}

// ---------------- launcher ----------------
extern "C" void kernel_launch(void* const* d_in, const int* in_sizes, int n_in,
                              void* d_out, int out_size)
{
    const float* x          = (const float*)d_in[0];
    const float* in_proj_w  = (const float*)d_in[1];
    const float* conv_w     = (const float*)d_in[2];
    const float* conv_b     = (const float*)d_in[3];
    const float* log_decay  = (const float*)d_in[4];
    const float* frequency  = (const float*)d_in[5];
    const float* coupling   = (const float*)d_in[6];
    const float* out_proj_w = (const float*)d_in[7];
    const float* gate_w     = (const float*)d_in[8];
    const float* gate_b     = (const float*)d_in[9];
    const float* mlp_w1     = (const float*)d_in[10];
    const float* mlp_b1     = (const float*)d_in[11];
    const float* mlp_w2     = (const float*)d_in[12];
    const float* mlp_b2     = (const float*)d_in[13];
    const float* ln1_g      = (const float*)d_in[14];
    const float* ln1_b      = (const float*)d_in[15];
    const float* ln2_g      = (const float*)d_in[16];
    const float* ln2_b      = (const float*)d_in[17];

    float* out = (float*)d_out;
    float* eig = out + OUT_ELEMS;

    __half *xn, *xn2, *hidden, *eig_h;
    float  *beta_l, *x1;
    __half *w_in, *w_out, *w_gate, *w_m1, *w_m2;
    cudaGetSymbolAddress((void**)&xn,     g_xn);
    cudaGetSymbolAddress((void**)&beta_l, g_beta_l);
    cudaGetSymbolAddress((void**)&eig_h,  g_eig_h);
    cudaGetSymbolAddress((void**)&x1,     g_x1);
    cudaGetSymbolAddress((void**)&xn2,    g_xn2);
    cudaGetSymbolAddress((void**)&hidden, g_hidden);
    cudaGetSymbolAddress((void**)&w_in,   g_w_in);
    cudaGetSymbolAddress((void**)&w_out,  g_w_out);
    cudaGetSymbolAddress((void**)&w_gate, g_w_gate);
    cudaGetSymbolAddress((void**)&w_m1,   g_w_m1);
    cudaGetSymbolAddress((void**)&w_m2,   g_w_m2);

    cudaFuncSetAttribute(gemm_fp16_kernel<0,false,64>,  cudaFuncAttributeMaxDynamicSharedMemorySize, SMEM_64);
    cudaFuncSetAttribute(gemm_fp16_kernel<1,true,128>,  cudaFuncAttributeMaxDynamicSharedMemorySize, SMEM_128);
    cudaFuncSetAttribute(gemm_fp16_kernel<3,false,128>, cudaFuncAttributeMaxDynamicSharedMemorySize, SMEM_128);
    cudaFuncSetAttribute(gemm_gate_kernel,              cudaFuncAttributeMaxDynamicSharedMemorySize, GK_SMEM);

    // 0. convert all weights to fp16 (single kernel)
    convert_weights<<<(SEG_OUT/2 + 255)/256, 256>>>(mlp_w1, mlp_w2, gate_w, in_proj_w, out_proj_w,
                                                    w_m1, w_m2, w_gate, w_in, w_out);
    // 1. xn = fp16(LN1(x))
    ln_kernel<<<BT, 256>>>(x, xn, ln1_g, ln1_b);
    // 2. beta_lin = xn @ in_proj_w.T  (64-row tiles: 256 CTAs)
    gemm_fp16_kernel<0,false,64><<<dim3(1, 256), 256, SMEM_64>>>(xn, w_in, beta_l, BT, 128, 1024,
                                                                 nullptr, nullptr);
    // 3. SSD (conv+silu + reverse scan + carry + coupling) -> eig, eig_h
    ssd_fused_kernel<<<Bb * NCH, 256>>>(beta_l, conv_w, conv_b, log_decay, frequency,
                                        coupling, eig, eig_h);
    // 4. x1 = x + sigmoid(xn @ gate_w.T + gate_b) * (eig @ out_proj_w.T)
    gemm_gate_kernel<<<dim3(8, 128), 256, GK_SMEM>>>(xn, w_gate, eig_h, w_out,
                                                     x, gate_b, x1);
    // 5. xn2 = fp16(LN2(x1))
    ln_kernel<<<BT, 256>>>(x1, xn2, ln2_g, ln2_b);
    // 6. hidden = fp16(silu(xn2 @ mlp_w1.T + b1))
    gemm_fp16_kernel<1,true,128><<<dim3(32, 128), 256, SMEM_128>>>(xn2, w_m1, hidden, BT, 4096, 1024,
                                                                   mlp_b1, nullptr);
    // 7. out = x1 + hidden @ mlp_w2.T + b2
    gemm_fp16_kernel<3,false,128><<<dim3(8, 128), 256, SMEM_128>>>(hidden, w_m2, out, BT, 1024, 4096,
                                                                   mlp_b2, x1);
}

// round 15
// speedup vs baseline: 1.3179x; 1.0022x over previous
#include <cuda_runtime.h>
#include <cuda_fp16.h>
#include <math.h>
#include <stdint.h>

// Shapes (fixed by the problem)
#define Bb   4
#define Tt   4096
#define Dm   1024
#define Kk   64
#define K2   128
#define Hh   4
#define Khd  16
#define NCH  64
#define BT   (Bb*Tt)       // 16384
#define MLP  4096
#define OUT_ELEMS (BT*Dm)  // 16777216

#define STAGES 3

// ---------------- scratch (static device memory; no allocation) ----------------
__device__ __half g_xn     [BT*Dm];
__device__ float  g_beta_l [BT*K2];
__device__ __half g_eig_h  [BT*K2];
__device__ float  g_x1     [BT*Dm];
__device__ __half g_xn2    [BT*Dm];
__device__ __half g_hidden [BT*MLP];
// fp16 weight copies
__device__ __half g_w_in   [K2*Dm];
__device__ __half g_w_out  [Dm*K2];
__device__ __half g_w_gate [Dm*Dm];
__device__ __half g_w_m1   [MLP*Dm];
__device__ __half g_w_m2   [Dm*MLP];

// ---------------- helpers ----------------
__device__ __forceinline__ void cp_async16(void* smem_dst, const void* gptr) {
    unsigned saddr = (unsigned)__cvta_generic_to_shared(smem_dst);
    asm volatile("cp.async.cg.shared.global [%0], [%1], 16;\n" :: "r"(saddr), "l"(gptr));
}
__device__ __forceinline__ void cp_commit() { asm volatile("cp.async.commit_group;\n"); }
__device__ __forceinline__ void cp_wait1()  { asm volatile("cp.async.wait_group 1;\n"); }

__device__ __forceinline__ void ldsm_x4(unsigned& r0, unsigned& r1, unsigned& r2, unsigned& r3,
                                        unsigned saddr) {
    asm volatile("ldmatrix.sync.aligned.m8n8.x4.shared.b16 {%0,%1,%2,%3}, [%4];"
                 : "=r"(r0), "=r"(r1), "=r"(r2), "=r"(r3) : "r"(saddr));
}

// ---------------- fused weight conversion fp32 -> fp16 (all 5 matrices) --------
// float4 loads (16B), half2x2 stores (8B); 4 elems per thread.
#define SEG_M1   4194304
#define SEG_M2   8388608
#define SEG_GATE 9437184
#define SEG_IN   9568256
#define SEG_OUT  9699328
__global__ void convert_weights(const float* __restrict__ m1f, const float* __restrict__ m2f,
                                const float* __restrict__ gf,  const float* __restrict__ inf_,
                                const float* __restrict__ outf,
                                __half* __restrict__ m1h, __half* __restrict__ m2h,
                                __half* __restrict__ gh,  __half* __restrict__ inh,
                                __half* __restrict__ outh)
{
    int j = (blockIdx.x * blockDim.x + threadIdx.x) * 4;
    const float* src; __half* dst; int off;
    if      (j < SEG_M1)   { src = m1f;  dst = m1h;  off = j; }
    else if (j < SEG_M2)   { src = m2f;  dst = m2h;  off = j - SEG_M1; }
    else if (j < SEG_GATE) { src = gf;   dst = gh;   off = j - SEG_M2; }
    else if (j < SEG_IN)   { src = inf_; dst = inh;  off = j - SEG_GATE; }
    else if (j < SEG_OUT)  { src = outf; dst = outh; off = j - SEG_IN; }
    else return;
    float4 v = *(const float4*)(src + off);
    __half2* d2 = (__half2*)(dst + off);
    d2[0] = __floats2half2_rn(v.x, v.y);
    d2[1] = __floats2half2_rn(v.z, v.w);
}

// ---------------- LayerNorm (writes fp16 output) ----------------
__global__ void ln_kernel(const float* __restrict__ in, __half* __restrict__ out,
                          const float* __restrict__ g, const float* __restrict__ bta)
{
    int row = blockIdx.x;
    const float4* p = (const float4*)(in + (size_t)row * Dm);
    float4 v = p[threadIdx.x];
    float s  = v.x + v.y + v.z + v.w;
    float ss = v.x*v.x + v.y*v.y + v.z*v.z + v.w*v.w;
    #pragma unroll
    for (int o = 16; o > 0; o >>= 1) {
        s  += __shfl_down_sync(0xffffffffu, s,  o);
        ss += __shfl_down_sync(0xffffffffu, ss, o);
    }
    __shared__ float rs[8], rss[8];
    __shared__ float smean, srstd;
    int warp = threadIdx.x >> 5, lane = threadIdx.x & 31;
    if (lane == 0) { rs[warp] = s; rss[warp] = ss; }
    __syncthreads();
    if (threadIdx.x == 0) {
        float ts = 0.f, tss = 0.f;
        #pragma unroll
        for (int w = 0; w < 8; w++) { ts += rs[w]; tss += rss[w]; }
        float mean = ts * (1.f/Dm);
        float var  = tss * (1.f/Dm) - mean*mean;
        smean = mean;
        srstd = rsqrtf(var + 1e-5f);
    }
    __syncthreads();
    float mean = smean, rstd = srstd;
    float4 gg = ((const float4*)g)[threadIdx.x];
    float4 bb = ((const float4*)bta)[threadIdx.x];
    __half2 h0 = __floats2half2_rn((v.x - mean) * rstd * gg.x + bb.x,
                                   (v.y - mean) * rstd * gg.y + bb.y);
    __half2 h1 = __floats2half2_rn((v.z - mean) * rstd * gg.z + bb.z,
                                   (v.w - mean) * rstd * gg.w + bb.w);
    __half2* dst = (__half2*)(out + (size_t)row * Dm) + threadIdx.x * 2;
    dst[0] = h0;
    dst[1] = h1;
}

// ---------------- fp16 tensor GEMM, 3-stage cp.async pipeline + ldmatrix --------
// C[m][n] = sum_k A[m][k]*B[n][k]; A,B fp16 row-major, Kd % 64 == 0.
// Block MROWS x NCOLS, 8 warps (2 x 4), warp tile (MROWS/2) x (NCOLS/4).
// EPI 0: C = acc ; 1: silu(acc+bias) ; 3: acc + bias + aux1. HOUT: fp16 store.
template<int EPI, bool HOUT, int MROWS, int NCOLS>
__global__ void __launch_bounds__(256)
gemm_fp16_kernel(const __half* __restrict__ A, const __half* __restrict__ Bw,
                 void* __restrict__ Cv, int M, int N, int Kd,
                 const float* __restrict__ bias,
                 const float* __restrict__ aux1)
{
    constexpr int MTC   = MROWS / 32;       // mt tiles per warp
    constexpr int NTW   = NCOLS / 32;       // nt tiles per warp
    constexpr int PW    = NTW / 2;          // B ldsm per ks
    constexpr int ATILE = MROWS * 128;      // bytes per A stage
    constexpr int BTILE = NCOLS * 128;      // bytes per B stage
    extern __shared__ char dsm[];
    const unsigned smem_u32 = (unsigned)__cvta_generic_to_shared(dsm);

    const int tid  = threadIdx.x;
    const int warp = tid >> 5, lane = tid & 31;
    const int wr = warp >> 2;
    const int wc = warp & 3;
    const int brow = blockIdx.y * MROWS, bcol = blockIdx.x * NCOLS;

    const int KT = Kd >> 6;

    auto issue = [&](int buf, int k0) {
        char* Atile = dsm + buf * ATILE;
        char* Btile = dsm + STAGES * ATILE + buf * BTILE;
        #pragma unroll
        for (int i = 0; i < MROWS / 32; i++) {
            int L = tid + i * 256;
            int row = L >> 3, c16 = L & 7;
            cp_async16(Atile + row * 128 + (((c16 ^ row) & 7) << 4),
                       A + (size_t)(brow + row) * Kd + k0 + c16 * 8);
        }
        #pragma unroll
        for (int i = 0; i < NCOLS / 32; i++) {
            int L = tid + i * 256;
            int row = L >> 3, c16 = L & 7;
            cp_async16(Btile + row * 128 + (((c16 ^ row) & 7) << 4),
                       Bw + (size_t)(bcol + row) * Kd + k0 + c16 * 8);
        }
    };

    float acc[MTC][NTW][4];
    #pragma unroll
    for (int m = 0; m < MTC; m++)
        #pragma unroll
        for (int n = 0; n < NTW; n++)
            #pragma unroll
            for (int i = 0; i < 4; i++) acc[m][n][i] = 0.f;

    issue(0, 0);  cp_commit();
    issue(1, 64); cp_commit();

    const int lm = lane & 7;
    int aoff[MTC], ars[MTC];
    {
        int rowsel = (lane >> 3) & 1;
        #pragma unroll
        for (int mt = 0; mt < MTC; mt++) {
            int row = wr * (MTC * 16) + mt * 16 + rowsel * 8 + lm;
            aoff[mt] = row * 128;
            ars[mt]  = row & 7;
        }
    }
    const int ghA = lane >> 4;
    int boff[PW], brs[PW];
    {
        int rowsel = lane >> 4;
        #pragma unroll
        for (int p = 0; p < PW; p++) {
            int n = wc * (NCOLS / 4) + p*16 + rowsel*8 + lm;
            boff[p] = n * 128;
            brs[p]  = n & 7;
        }
    }
    const int ghB = (lane >> 3) & 1;

    const int ra = lane >> 2;
    const int c0 = lane & 3;

    for (int kt = 0; kt < KT; kt++) {
        cp_wait1();
        __syncthreads();
        if (kt + 2 < KT) issue((kt + 2) % STAGES, (kt + 2) * 64);
        cp_commit();

        const int buf = kt % STAGES;
        const unsigned Abase = smem_u32 + buf * ATILE;
        const unsigned Bbase = smem_u32 + STAGES * ATILE + buf * BTILE;

        #pragma unroll
        for (int ks = 0; ks < 4; ks++) {
            unsigned af[MTC][4], bf[NTW][2];
            const int gA = 2*ks + ghA;
            #pragma unroll
            for (int mt = 0; mt < MTC; mt++) {
                unsigned ad = Abase + aoff[mt] + (unsigned)(((gA ^ ars[mt]) & 7) << 4);
                ldsm_x4(af[mt][0], af[mt][1], af[mt][2], af[mt][3], ad);
            }
            const int gB = 2*ks + ghB;
            #pragma unroll
            for (int p = 0; p < PW; p++) {
                unsigned bd = Bbase + boff[p] + (unsigned)(((gB ^ brs[p]) & 7) << 4);
                ldsm_x4(bf[2*p][0], bf[2*p][1], bf[2*p+1][0], bf[2*p+1][1], bd);
            }
            #pragma unroll
            for (int mt = 0; mt < MTC; mt++)
                #pragma unroll
                for (int nt = 0; nt < NTW; nt++)
                    asm volatile(
                        "mma.sync.aligned.m16n8k16.row.col.f32.f16.f16.f32 "
                        "{%0,%1,%2,%3}, {%4,%5,%6,%7}, {%8,%9}, {%0,%1,%2,%3};"
                        : "+f"(acc[mt][nt][0]), "+f"(acc[mt][nt][1]),
                          "+f"(acc[mt][nt][2]), "+f"(acc[mt][nt][3])
                        : "r"(af[mt][0]), "r"(af[mt][1]), "r"(af[mt][2]), "r"(af[mt][3]),
                          "r"(bf[nt][0]), "r"(bf[nt][1]));
        }
    }

    #pragma unroll
    for (int mt = 0; mt < MTC; mt++) {
        #pragma unroll
        for (int half = 0; half < 2; half++) {
            int row = brow + wr * (MTC * 16) + mt*16 + ra + half*8;
            #pragma unroll
            for (int nt = 0; nt < NTW; nt++) {
                int col = bcol + wc * (NCOLS / 4) + nt*8 + c0*2;
                size_t idx = (size_t)row * N + col;
                float v0 = acc[mt][nt][half*2 + 0];
                float v1 = acc[mt][nt][half*2 + 1];
                float2 o;
                if (EPI == 0) {
                    o.x = v0; o.y = v1;
                } else if (EPI == 1) {
                    v0 += bias[col]; v1 += bias[col+1];
                    o.x = v0 / (1.f + expf(-v0));
                    o.y = v1 / (1.f + expf(-v1));
                } else { // EPI == 3
                    float2 a1v = *(const float2*)(aux1 + idx);
                    o.x = v0 + bias[col]   + a1v.x;
                    o.y = v1 + bias[col+1] + a1v.y;
                }
                if (HOUT) {
                    *(__half2*)((__half*)Cv + idx) = __floats2half2_rn(o.x, o.y);
                } else {
                    *(float2*)((float*)Cv + idx) = o;
                }
            }
        }
    }
}

#define BTILE_BYTES 16384
#define SMEM_128 (STAGES * 2 * BTILE_BYTES)                  // 98304
#define SMEM_IN  (STAGES * (64*128) + STAGES * (64*128))     // 49152

// ---------------- fused gate+out_proj dual GEMM ----------------
// Phase-2 operands (eig_h, Wo) prefetched at kernel entry into dedicated SMEM.
#define GK_A2  (STAGES * 2 * BTILE_BYTES)        // 98304: 2 x 16KB A2 buffers
#define GK_B2  (GK_A2 + 32768)                   // 2 x 16KB B2 buffers
#define GK_G   (GK_B2 + 32768)                   // 32KB g park
#define GK_SMEM (GK_G + 32768)                   // 196608
__global__ void __launch_bounds__(256)
gemm_gate_kernel(const __half* __restrict__ Axn, const __half* __restrict__ Wg,
                 const __half* __restrict__ Aeig, const __half* __restrict__ Wo,
                 const float* __restrict__ xres, const float* __restrict__ gate_b,
                 float* __restrict__ x1)
{
    extern __shared__ char dsm[];
    const unsigned smem_u32 = (unsigned)__cvta_generic_to_shared(dsm);
    const int Nn = Dm;

    const int tid  = threadIdx.x;
    const int warp = tid >> 5, lane = tid & 31;
    const int wr = warp >> 2;
    const int wc = warp & 3;
    const int brow = blockIdx.y * 128, bcol = blockIdx.x * 128;

    const int KT = Dm >> 6;    // 16

    // prefetch phase-2 operands as the FIRST cp.async group (drains at kt=0 wait)
    #pragma unroll
    for (int bfi = 0; bfi < 2; bfi++) {
        #pragma unroll
        for (int i = 0; i < 4; i++) {
            int L = tid + i * 256;
            int row = L >> 3, c16 = L & 7;
            int dst = row * 128 + (((c16 ^ row) & 7) << 4);
            cp_async16(dsm + GK_A2 + bfi * 16384 + dst,
                       Aeig + (size_t)(brow + row) * 128 + bfi * 64 + c16 * 8);
            cp_async16(dsm + GK_B2 + bfi * 16384 + dst,
                       Wo   + (size_t)(bcol + row) * 128 + bfi * 64 + c16 * 8);
        }
    }
    cp_commit();

    auto issue = [&](int buf, int k0) {
        char* Atile = dsm + buf * BTILE_BYTES;
        char* Btile = dsm + STAGES * BTILE_BYTES + buf * BTILE_BYTES;
        #pragma unroll
        for (int i = 0; i < 4; i++) {
            int L = tid + i * 256;
            int row = L >> 3, c16 = L & 7;
            int dst = row * 128 + (((c16 ^ row) & 7) << 4);
            cp_async16(Atile + dst, Axn + (size_t)(brow + row) * Dm + k0 + c16 * 8);
            cp_async16(Btile + dst, Wg  + (size_t)(bcol + row) * Dm + k0 + c16 * 8);
        }
    };

    float acc[4][4][4];
    #pragma unroll
    for (int m = 0; m < 4; m++)
        #pragma unroll
        for (int n = 0; n < 4; n++)
            #pragma unroll
            for (int i = 0; i < 4; i++) acc[m][n][i] = 0.f;

    issue(0, 0);  cp_commit();
    issue(1, 64); cp_commit();

    const int lm = lane & 7;
    int aoff[4], ars[4];
    {
        int rowsel = (lane >> 3) & 1;
        #pragma unroll
        for (int mt = 0; mt < 4; mt++) {
            int row = wr*64 + mt*16 + rowsel*8 + lm;
            aoff[mt] = row * 128;
            ars[mt]  = row & 7;
        }
    }
    const int ghA = lane >> 4;
    int boff[2], brs[2];
    {
        int rowsel = lane >> 4;
        #pragma unroll
        for (int p = 0; p < 2; p++) {
            int n = wc*32 + p*16 + rowsel*8 + lm;
            boff[p] = n * 128;
            brs[p]  = n & 7;
        }
    }
    const int ghB = (lane >> 3) & 1;

    const int ra = lane >> 2;
    const int c0 = lane & 3;

    // ---- phase 1: gate GEMM (K = 1024) ----
    for (int kt = 0; kt < KT; kt++) {
        cp_wait1();
        __syncthreads();
        if (kt + 2 < KT) issue((kt + 2) % STAGES, (kt + 2) * 64);
        cp_commit();

        const int buf = kt % STAGES;
        const unsigned Abase = smem_u32 + buf * BTILE_BYTES;
        const unsigned Bbase = smem_u32 + STAGES * BTILE_BYTES + buf * BTILE_BYTES;

        #pragma unroll
        for (int ks = 0; ks < 4; ks++) {
            unsigned af[4][4], bf[4][2];
            const int gA = 2*ks + ghA;
            #pragma unroll
            for (int mt = 0; mt < 4; mt++) {
                unsigned ad = Abase + aoff[mt] + (unsigned)(((gA ^ ars[mt]) & 7) << 4);
                ldsm_x4(af[mt][0], af[mt][1], af[mt][2], af[mt][3], ad);
            }
            const int gB = 2*ks + ghB;
            #pragma unroll
            for (int p = 0; p < 2; p++) {
                unsigned bd = Bbase + boff[p] + (unsigned)(((gB ^ brs[p]) & 7) << 4);
                ldsm_x4(bf[2*p][0], bf[2*p][1], bf[2*p+1][0], bf[2*p+1][1], bd);
            }
            #pragma unroll
            for (int mt = 0; mt < 4; mt++)
                #pragma unroll
                for (int nt = 0; nt < 4; nt++)
                    asm volatile(
                        "mma.sync.aligned.m16n8k16.row.col.f32.f16.f16.f32 "
                        "{%0,%1,%2,%3}, {%4,%5,%6,%7}, {%8,%9}, {%0,%1,%2,%3};"
                        : "+f"(acc[mt][nt][0]), "+f"(acc[mt][nt][1]),
                          "+f"(acc[mt][nt][2]), "+f"(acc[mt][nt][3])
                        : "r"(af[mt][0]), "r"(af[mt][1]), "r"(af[mt][2]), "r"(af[mt][3]),
                          "r"(bf[nt][0]), "r"(bf[nt][1]));
        }
    }

    // g = sigmoid(acc + gate_b), parked fp16 in dedicated region (own-thread readback)
    #pragma unroll
    for (int mt = 0; mt < 4; mt++) {
        #pragma unroll
        for (int half = 0; half < 2; half++) {
            #pragma unroll
            for (int nt = 0; nt < 4; nt++) {
                int col = bcol + wc*32 + nt*8 + c0*2;
                float v0 = acc[mt][nt][half*2 + 0] + gate_b[col];
                float v1 = acc[mt][nt][half*2 + 1] + gate_b[col+1];
                __half2 gv = __floats2half2_rn(1.f / (1.f + expf(-v0)),
                                               1.f / (1.f + expf(-v1)));
                int j = mt*8 + half*4 + nt;          // 0..31
                *(__half2*)(dsm + GK_G + (j * 256 + tid) * 4) = gv;
            }
        }
    }

    // zero acc for phase 2
    #pragma unroll
    for (int m = 0; m < 4; m++)
        #pragma unroll
        for (int n = 0; n < 4; n++)
            #pragma unroll
            for (int i = 0; i < 4; i++) acc[m][n][i] = 0.f;

    // ---- phase 2: out_proj GEMM (K = 128) from prefetched tiles ----
    #pragma unroll
    for (int bfi = 0; bfi < 2; bfi++) {
        const unsigned Abase = smem_u32 + GK_A2 + bfi * 16384;
        const unsigned Bbase = smem_u32 + GK_B2 + bfi * 16384;
        #pragma unroll
        for (int ks = 0; ks < 4; ks++) {
            unsigned af[4][4], bf[4][2];
            const int gA = 2*ks + ghA;
            #pragma unroll
            for (int mt = 0; mt < 4; mt++) {
                unsigned ad = Abase + aoff[mt] + (unsigned)(((gA ^ ars[mt]) & 7) << 4);
                ldsm_x4(af[mt][0], af[mt][1], af[mt][2], af[mt][3], ad);
            }
            const int gB = 2*ks + ghB;
            #pragma unroll
            for (int p = 0; p < 2; p++) {
                unsigned bd = Bbase + boff[p] + (unsigned)(((gB ^ brs[p]) & 7) << 4);
                ldsm_x4(bf[2*p][0], bf[2*p][1], bf[2*p+1][0], bf[2*p+1][1], bd);
            }
            #pragma unroll
            for (int mt = 0; mt < 4; mt++)
                #pragma unroll
                for (int nt = 0; nt < 4; nt++)
                    asm volatile(
                        "mma.sync.aligned.m16n8k16.row.col.f32.f16.f16.f32 "
                        "{%0,%1,%2,%3}, {%4,%5,%6,%7}, {%8,%9}, {%0,%1,%2,%3};"
                        : "+f"(acc[mt][nt][0]), "+f"(acc[mt][nt][1]),
                          "+f"(acc[mt][nt][2]), "+f"(acc[mt][nt][3])
                        : "r"(af[mt][0]), "r"(af[mt][1]), "r"(af[mt][2]), "r"(af[mt][3]),
                          "r"(bf[nt][0]), "r"(bf[nt][1]));
        }
    }

    // epilogue: x1 = x + g * h
    #pragma unroll
    for (int mt = 0; mt < 4; mt++) {
        #pragma unroll
        for (int half = 0; half < 2; half++) {
            int row = brow + wr*64 + mt*16 + ra + half*8;
            #pragma unroll
            for (int nt = 0; nt < 4; nt++) {
                int col = bcol + wc*32 + nt*8 + c0*2;
                size_t idx = (size_t)row * Nn + col;
                int j = mt*8 + half*4 + nt;
                float2 gv = __half22float2(*(const __half2*)(dsm + GK_G + (j * 256 + tid) * 4));
                float2 xv = *(const float2*)(xres + idx);
                float2 o;
                o.x = xv.x + gv.x * acc[mt][nt][half*2 + 0];
                o.y = xv.y + gv.y * acc[mt][nt][half*2 + 1];
                *(float2*)(x1 + idx) = o;
            }
        }
    }
}

// ---------------- fused SSD: conv+SiLU + anti-causal scan + coupling + eig ------
__global__ void __launch_bounds__(256)
ssd_fused_kernel(const float* __restrict__ beta_l,
                 const float* __restrict__ conv_w,
                 const float* __restrict__ conv_b,
                 const float* __restrict__ log_decay,
                 const float* __restrict__ freq,
                 const float* __restrict__ coupling,
                 float* __restrict__ eig,
                 __half* __restrict__ eig_h)
{
    __shared__ float sb[64 * 128];
    __shared__ float scoup[Hh * Khd * Khd];
    int b  = blockIdx.x >> 6;
    int ch = blockIdx.x & 63;
    int tid = threadIdx.x;
    for (int i = tid; i < Hh * Khd * Khd; i += 256)
        scoup[i] = coupling[i];

    {
        int c  = tid & 127;
        int hf = tid >> 7;
        int i0 = hf * 32;
        float w0 = conv_w[c*4+0], w1 = conv_w[c*4+1],
              w2 = conv_w[c*4+2], w3 = conv_w[c*4+3];
        float cb = conv_b[c];
        int t0 = ch * 64 + i0;
        size_t gbase = ((size_t)(b * Tt + t0)) * 128 + c;
        float p0 = (t0 - 3 >= 0) ? beta_l[gbase - 3*128] : 0.f;
        float p1 = (t0 - 2 >= 0) ? beta_l[gbase - 2*128] : 0.f;
        float p2 = (t0 - 1 >= 0) ? beta_l[gbase - 1*128] : 0.f;
        #pragma unroll 4
        for (int i = 0; i < 32; i++) {
            float cur = beta_l[gbase + (size_t)i * 128];
            float a = cb + p0*w0 + p1*w1 + p2*w2 + cur*w3;
            sb[(i0 + i) * 128 + c] = a / (1.f + expf(-a));
            p0 = p1; p1 = p2; p2 = cur;
        }
    }
    __syncthreads();

    if (tid < 64) {
        int k = tid;
        float mag = 1.f / (1.f + expf(-log_decay[k]));
        float f   = freq[k];
        float lr = mag * cosf(f), li = mag * sinf(f);
        float zr = 0.f, zi = 0.f;
        for (int i = 63; i >= 0; i--) {
            float br = sb[i * 128 + k];
            float bi = sb[i * 128 + 64 + k];
            float nr = lr * zr - li * zi + br;
            float ni = lr * zi + li * zr + bi;
            zr = nr; zi = ni;
            sb[i * 128 + k]      = zr;
            sb[i * 128 + 64 + k] = zi;
        }
        if (ch > 0) {
            size_t gb = ((size_t)(b * Tt + ch * 64 - 4)) * 128;
            float ar = conv_b[k], ai = conv_b[64 + k];
            #pragma unroll
            for (int j = 0; j < 4; j++) {
                ar += beta_l[gb + (size_t)j * 128 + k]      * conv_w[k * 4 + j];
                ai += beta_l[gb + (size_t)j * 128 + 64 + k] * conv_w[(64 + k) * 4 + j];
            }
            sb[k]      += ar / (1.f + expf(-ar));
            sb[64 + k] += ai / (1.f + expf(-ai));
        }
    }
    __syncthreads();

    for (int task = tid; task < 64 * 64; task += 256) {
        int i  = task >> 6;
        int ko = task & 63;
        int h = ko >> 4, j = ko & 15;
        const float* cw = scoup + h * (Khd * Khd) + j * Khd;
        const float* rowr = sb + i * 128 + h * Khd;
        const float* rowi = rowr + 64;
        float or_ = 0.f, oi_ = 0.f;
        #pragma unroll
        for (int kk = 0; kk < Khd; kk++) {
            float w = cw[kk];
            or_ += w * rowr[kk];
            oi_ += w * rowi[kk];
        }
        size_t e = (size_t)(b * Tt + ch * 64 + i) * 128;
        eig[e + ko]      = or_;
        eig[e + 64 + ko] = oi_;
        eig_h[e + ko]      = __float2half_rn(or_);
        eig_h[e + 64 + ko] = __float2half_rn(oi_);
    }
}

// ---------------- launcher ----------------
extern "C" void kernel_launch(void* const* d_in, const int* in_sizes, int n_in,
                              void* d_out, int out_size)
{
    const float* x          = (const float*)d_in[0];
    const float* in_proj_w  = (const float*)d_in[1];
    const float* conv_w     = (const float*)d_in[2];
    const float* conv_b     = (const float*)d_in[3];
    const float* log_decay  = (const float*)d_in[4];
    const float* frequency  = (const float*)d_in[5];
    const float* coupling   = (const float*)d_in[6];
    const float* out_proj_w = (const float*)d_in[7];
    const float* gate_w     = (const float*)d_in[8];
    const float* gate_b     = (const float*)d_in[9];
    const float* mlp_w1     = (const float*)d_in[10];
    const float* mlp_b1     = (const float*)d_in[11];
    const float* mlp_w2     = (const float*)d_in[12];
    const float* mlp_b2     = (const float*)d_in[13];
    const float* ln1_g      = (const float*)d_in[14];
    const float* ln1_b      = (const float*)d_in[15];
    const float* ln2_g      = (const float*)d_in[16];
    const float* ln2_b      = (const float*)d_in[17];

    float* out = (float*)d_out;
    float* eig = out + OUT_ELEMS;

    __half *xn, *xn2, *hidden, *eig_h;
    float  *beta_l, *x1;
    __half *w_in, *w_out, *w_gate, *w_m1, *w_m2;
    cudaGetSymbolAddress((void**)&xn,     g_xn);
    cudaGetSymbolAddress((void**)&beta_l, g_beta_l);
    cudaGetSymbolAddress((void**)&eig_h,  g_eig_h);
    cudaGetSymbolAddress((void**)&x1,     g_x1);
    cudaGetSymbolAddress((void**)&xn2,    g_xn2);
    cudaGetSymbolAddress((void**)&hidden, g_hidden);
    cudaGetSymbolAddress((void**)&w_in,   g_w_in);
    cudaGetSymbolAddress((void**)&w_out,  g_w_out);
    cudaGetSymbolAddress((void**)&w_gate, g_w_gate);
    cudaGetSymbolAddress((void**)&w_m1,   g_w_m1);
    cudaGetSymbolAddress((void**)&w_m2,   g_w_m2);

    cudaFuncSetAttribute(gemm_fp16_kernel<0,false,64,64>,   cudaFuncAttributeMaxDynamicSharedMemorySize, SMEM_IN);
    cudaFuncSetAttribute(gemm_fp16_kernel<1,true,128,128>,  cudaFuncAttributeMaxDynamicSharedMemorySize, SMEM_128);
    cudaFuncSetAttribute(gemm_fp16_kernel<3,false,128,128>, cudaFuncAttributeMaxDynamicSharedMemorySize, SMEM_128);
    cudaFuncSetAttribute(gemm_gate_kernel,                  cudaFuncAttributeMaxDynamicSharedMemorySize, GK_SMEM);

    // 0. convert all weights to fp16 (single kernel, float4 loads)
    convert_weights<<<(SEG_OUT/4 + 255)/256, 256>>>(mlp_w1, mlp_w2, gate_w, in_proj_w, out_proj_w,
                                                    w_m1, w_m2, w_gate, w_in, w_out);
    // 1. xn = fp16(LN1(x))
    ln_kernel<<<BT, 256>>>(x, xn, ln1_g, ln1_b);
    // 2. beta_lin = xn @ in_proj_w.T  (64x64 tiles: 512 CTAs)
    gemm_fp16_kernel<0,false,64,64><<<dim3(2, 256), 256, SMEM_IN>>>(xn, w_in, beta_l, BT, 128, 1024,
                                                                    nullptr, nullptr);
    // 3. SSD (conv+silu + reverse scan + carry + coupling) -> eig, eig_h
    ssd_fused_kernel<<<Bb * NCH, 256>>>(beta_l, conv_w, conv_b, log_decay, frequency,
                                        coupling, eig, eig_h);
    // 4. x1 = x + sigmoid(xn @ gate_w.T + gate_b) * (eig @ out_proj_w.T)
    gemm_gate_kernel<<<dim3(8, 128), 256, GK_SMEM>>>(xn, w_gate, eig_h, w_out,
                                                     x, gate_b, x1);
    // 5. xn2 = fp16(LN2(x1))
    ln_kernel<<<BT, 256>>>(x1, xn2, ln2_g, ln2_b);
    // 6. hidden = fp16(silu(xn2 @ mlp_w1.T + b1))
    gemm_fp16_kernel<1,true,128,128><<<dim3(32, 128), 256, SMEM_128>>>(xn2, w_m1, hidden, BT, 4096, 1024,
                                                                       mlp_b1, nullptr);
    // 7. out = x1 + hidden @ mlp_w2.T + b2
    gemm_fp16_kernel<3,false,128,128><<<dim3(8, 128), 256, SMEM_128>>>(hidden, w_m2, out, BT, 1024, 4096,
                                                                       mlp_b2, x1);
}